// round 10
// baseline (speedup 1.0000x reference)
#include <cuda_runtime.h>
#include <math.h>

#define BATCH 128
#define CCH   128
#define LL    256
#define NHEADS 8
#define EQK   128
#define EV    512
#define EALL  768   // 128 q + 128 k + 512 v

// ---------------- scratch (device globals; no allocations) ----------------
__device__ float g_proj[BATCH * EALL * LL];
__device__ float g_posatt[BATCH * EV * LL];
__device__ float g_outcha[BATCH * CCH * LL];
__device__ float g_mid[BATCH * CCH * LL];
__device__ float g_wallt[128 * EALL];
__device__ float g_ball[EALL];
__device__ float g_wtpos[4608 * 128];
__device__ float g_wtfuse[1152 * 128];

// ---------------- packed f32x2 helpers ----------------
typedef unsigned long long u64;
__device__ __forceinline__ u64 pk2(float lo, float hi) {
    u64 r; asm("mov.b64 %0, {%1, %2};" : "=l"(r) : "f"(lo), "f"(hi)); return r;
}
__device__ __forceinline__ void fma2(u64& d, u64 a, u64 b) {
    asm("fma.rn.f32x2 %0, %1, %2, %0;" : "+l"(d) : "l"(a), "l"(b));
}
__device__ __forceinline__ void mul2(u64& d, u64 a) {
    asm("mul.rn.f32x2 %0, %0, %1;" : "+l"(d) : "l"(a));
}
__device__ __forceinline__ float2 upk2(u64 v) {
    float2 r; asm("mov.b64 {%0, %1}, %2;" : "=f"(r.x), "=f"(r.y) : "l"(v)); return r;
}

// =====================================================================
// Kernel 0: one-time weight transposes
// =====================================================================
__global__ void k_setup(const float* __restrict__ wq, const float* __restrict__ wk,
                        const float* __restrict__ wv,
                        const float* __restrict__ bq, const float* __restrict__ bk,
                        const float* __restrict__ bv,
                        const float* __restrict__ pwo, const float* __restrict__ fw)
{
    const int total = 98304 + 589824 + 147456 + 768;
    for (int t = blockIdx.x * 256 + threadIdx.x; t < total; t += gridDim.x * 256) {
        if (t < 98304) {
            int c = t / 768, e = t - c * 768;
            float w;
            if (e < 128)      w = wq[e * 128 + c];
            else if (e < 256) w = wk[(e - 128) * 128 + c];
            else              w = wv[(e - 256) * 128 + c];
            g_wallt[t] = w;
        } else if (t < 98304 + 589824) {
            int t2 = t - 98304;
            int k = t2 >> 7, m = t2 & 127;
            int tap = k >> 9, ci = k & 511;
            g_wtpos[t2] = pwo[(m * 512 + ci) * 9 + tap];
        } else if (t < 98304 + 589824 + 147456) {
            int t3 = t - 98304 - 589824;
            int k = t3 >> 7, m = t3 & 127;
            int tap = k >> 7, ci = k & 127;
            g_wtfuse[t3] = fw[(m * 128 + ci) * 9 + tap];
        } else {
            int e = t - (98304 + 589824 + 147456);
            g_ball[e] = (e < 128) ? bq[e] : ((e < 256) ? bk[e - 128] : bv[e - 256]);
        }
    }
}

// ---------------- shared GEMM micro-kernel macro (8x8, f32x2) ----------------
#define GEMM_COMPUTE_32(As, Bs, acc2, ty, tx)                                   \
    _Pragma("unroll")                                                           \
    for (int kk = 0; kk < 32; kk++) {                                           \
        float4 a0 = *(const float4*)&As[kk][(ty) * 8];                          \
        float4 a1 = *(const float4*)&As[kk][(ty) * 8 + 4];                      \
        float4 b0 = *(const float4*)&Bs[kk][(tx) * 8];                          \
        float4 b1 = *(const float4*)&Bs[kk][(tx) * 8 + 4];                      \
        u64 bp[4] = { pk2(b0.x, b0.y), pk2(b0.z, b0.w),                         \
                      pk2(b1.x, b1.y), pk2(b1.z, b1.w) };                       \
        float av[8] = { a0.x, a0.y, a0.z, a0.w, a1.x, a1.y, a1.z, a1.w };       \
        _Pragma("unroll")                                                       \
        for (int i = 0; i < 8; i++) {                                           \
            u64 ad = pk2(av[i], av[i]);                                         \
            _Pragma("unroll")                                                   \
            for (int jp = 0; jp < 4; jp++) fma2(acc2[i][jp], ad, bp[jp]);       \
        }                                                                       \
    }

// =====================================================================
// Kernel 1: positional projections (M=768, N=256, K=128)
// =====================================================================
__global__ __launch_bounds__(256, 2) void k_proj(const float* __restrict__ x)
{
    const int b  = blockIdx.z;
    const int m0 = blockIdx.y * 128;
    const int n0 = blockIdx.x * 128;
    const int tid = threadIdx.x;
    const int tx = tid & 15, ty = tid >> 4;

    __shared__ float As[32][132];
    __shared__ float Bs[32][132];
    u64 acc2[8][4] = {};

    for (int k0 = 0; k0 < 128; k0 += 32) {
        #pragma unroll
        for (int r = 0; r < 16; r++) {
            int e = r * 256 + tid;
            int kk = e >> 7, m = e & 127;
            As[kk][m] = g_wallt[(k0 + kk) * EALL + m0 + m];
            Bs[kk][m] = x[(b * CCH + k0 + kk) * LL + n0 + m];
        }
        __syncthreads();
        GEMM_COMPUTE_32(As, Bs, acc2, ty, tx)
        __syncthreads();
    }

    #pragma unroll
    for (int i = 0; i < 8; i++) {
        int e = m0 + ty * 8 + i;
        float bias = g_ball[e];
        float* dst = &g_proj[(b * EALL + e) * LL + n0 + tx * 8];
        #pragma unroll
        for (int jp = 0; jp < 4; jp++) {
            float2 v = upk2(acc2[i][jp]);
            dst[jp * 2 + 0] = v.x + bias;
            dst[jp * 2 + 1] = v.y + bias;
        }
    }
}

// =====================================================================
// Kernel 2: positional attention per (b,h). Online softmax, f32x2 PV.
// =====================================================================
#define SMEM_POSATT ((256*20 + 256*68) * 4)
__global__ __launch_bounds__(256) void k_pos_attn()
{
    const int h = blockIdx.x, b = blockIdx.y;
    const int tid = threadIdx.x;
    extern __shared__ float sm2[];
    float* sk = sm2;
    float* sv = sk + 256 * 20;

    #pragma unroll
    for (int r = 0; r < 16; r++)
        sk[tid * 20 + r] = g_proj[(b * EALL + 128 + h * 16 + r) * LL + tid];
    #pragma unroll
    for (int r = 0; r < 64; r++)
        sv[tid * 68 + r] = g_proj[(b * EALL + 256 + h * 64 + r) * LL + tid];

    u64 qp[8];
    {
        float q[16];
        #pragma unroll
        for (int r = 0; r < 16; r++)
            q[r] = g_proj[(b * EALL + h * 16 + r) * LL + tid];
        #pragma unroll
        for (int i = 0; i < 8; i++) qp[i] = pk2(q[2 * i], q[2 * i + 1]);
    }
    __syncthreads();

    float mx = -1e30f, s = 0.f;
    u64 acc2[32];
    #pragma unroll
    for (int j = 0; j < 32; j++) acc2[j] = 0ull;

    for (int k = 0; k < 256; k++) {
        const float4* kp = (const float4*)(sk + k * 20);
        u64 d2 = 0ull;
        #pragma unroll
        for (int q4 = 0; q4 < 4; q4++) {
            float4 kv = kp[q4];
            fma2(d2, qp[q4 * 2 + 0], pk2(kv.x, kv.y));
            fma2(d2, qp[q4 * 2 + 1], pk2(kv.z, kv.w));
        }
        float2 dd = upk2(d2);
        float sc = (dd.x + dd.y) * 0.25f;

        float p;
        if (sc > mx) {
            float corr = __expf(mx - sc);
            s *= corr;
            u64 c2 = pk2(corr, corr);
            #pragma unroll
            for (int j = 0; j < 32; j++) mul2(acc2[j], c2);
            mx = sc; p = 1.f;
        } else {
            p = __expf(sc - mx);
        }
        s += p;

        u64 pp = pk2(p, p);
        const float4* vp = (const float4*)(sv + k * 68);
        #pragma unroll
        for (int j4 = 0; j4 < 16; j4++) {
            float4 v = vp[j4];
            fma2(acc2[j4 * 2 + 0], pp, pk2(v.x, v.y));
            fma2(acc2[j4 * 2 + 1], pp, pk2(v.z, v.w));
        }
    }
    float inv = 1.f / s;
    #pragma unroll
    for (int j = 0; j < 32; j++) {
        float2 v = upk2(acc2[j]);
        g_posatt[(b * EV + h * 64 + 2 * j + 0) * LL + tid] = v.x * inv;
        g_posatt[(b * EV + h * 64 + 2 * j + 1) * LL + tid] = v.y * inv;
    }
}

// =====================================================================
// Kernel 3: channel attention per (b,h'), fully fused — 512 threads.
// Same fusion and memory traffic as the proven R2 version; per-thread
// work halved (phase1 4x8 micro-tile, phase3 2x4) to cut registers and
// double resident warps (8 -> 16 per SM).
// smem: sS[128][133] + sA[128][36] + sB[128][36] = 104960 B
// =====================================================================
#define SMEM_CHAATT ((128*133 + 128*36*2) * 4)
__global__ __launch_bounds__(512) void k_cha_attn(
    const float* __restrict__ x,
    const float* __restrict__ wq, const float* __restrict__ bq,
    const float* __restrict__ wk, const float* __restrict__ bk,
    const float* __restrict__ wv, const float* __restrict__ bv,
    const float* __restrict__ wo, const float* __restrict__ bo,
    const float* __restrict__ gammap)
{
    const int h = blockIdx.x, b = blockIdx.y;
    const int tid = threadIdx.x;
    const int tx = tid & 15, ty2 = tid >> 4;   // tx 0..15, ty2 0..31
    extern __shared__ float sm3[];
    float* sS = sm3;               // [128][133]
    float* sA = sS + 128 * 133;    // [128][36]
    float* sB = sA + 128 * 36;     // [128][36]

    // ---- phase 1: S[c][d] = (1/16) sum_l pq[c,l] pk[d,l]; 4x8 per thread ----
    u64 facc2[4][4] = {};
    for (int l0 = 0; l0 < 256; l0 += 32) {
        __syncthreads();
        #pragma unroll
        for (int r = 0; r < 8; r++) {
            int e = r * 512 + tid;
            int c = e >> 5, lc = e & 31;
            int j = h * 128 + c;
            float xv = x[(b * CCH + (j >> 3)) * LL + l0 + lc];
            sA[c * 36 + lc] = xv * wq[j] + bq[j];
            sB[c * 36 + lc] = xv * wk[j] + bk[j];
        }
        __syncthreads();
        #pragma unroll
        for (int lc = 0; lc < 32; lc++) {
            float a[4], bbv[8];
            #pragma unroll
            for (int i = 0; i < 4; i++) a[i]   = sA[(ty2 * 4 + i) * 36 + lc];
            #pragma unroll
            for (int j = 0; j < 8; j++) bbv[j] = sB[(tx + 16 * j) * 36 + lc];
            u64 bp[4] = { pk2(bbv[0], bbv[1]), pk2(bbv[2], bbv[3]),
                          pk2(bbv[4], bbv[5]), pk2(bbv[6], bbv[7]) };
            #pragma unroll
            for (int i = 0; i < 4; i++) {
                u64 ad = pk2(a[i], a[i]);
                #pragma unroll
                for (int jp = 0; jp < 4; jp++) fma2(facc2[i][jp], ad, bp[jp]);
            }
        }
    }
    __syncthreads();
    #pragma unroll
    for (int i = 0; i < 4; i++)
        #pragma unroll
        for (int jp = 0; jp < 4; jp++) {
            float2 v = upk2(facc2[i][jp]);
            sS[(ty2 * 4 + i) * 133 + tx + 16 * (2 * jp + 0)] = v.x * 0.0625f;
            sS[(ty2 * 4 + i) * 133 + tx + 16 * (2 * jp + 1)] = v.y * 0.0625f;
        }
    __syncthreads();

    // ---- phase 2: softmax over d (128 rows) ----
    if (tid < 128) {
        float m = -1e30f;
        for (int d = 0; d < 128; d++) m = fmaxf(m, sS[tid * 133 + d]);
        float sum = 0.f;
        for (int d = 0; d < 128; d++) {
            float p = __expf(sS[tid * 133 + d] - m);
            sS[tid * 133 + d] = p;
            sum += p;
        }
        float invs = 1.f / sum;
        for (int d = 0; d < 128; d++) sS[tid * 133 + d] *= invs;
    }
    __syncthreads();

    // ---- phase 3: out = P @ pv (2x4 per thread), grouped proj, residual ----
    const float gcha = gammap[0];
    const int cg = tid >> 3;      // 0..63  -> c = cg*2 + i
    const int lg = tid & 7;       // 0..7   -> lc = lg*4 + j
    for (int l0 = 0; l0 < 256; l0 += 32) {
        __syncthreads();
        #pragma unroll
        for (int r = 0; r < 8; r++) {
            int e = r * 512 + tid;
            int c = e >> 5, lc = e & 31;
            int j = h * 128 + c;
            float xv = x[(b * CCH + (j >> 3)) * LL + l0 + lc];
            sA[c * 36 + lc] = xv * wv[j] + bv[j];
        }
        __syncthreads();

        u64 pacc[2][2] = {};
        for (int d = 0; d < 128; d++) {
            float4 v = *(const float4*)&sA[d * 36 + lg * 4];
            u64 v01 = pk2(v.x, v.y), v23 = pk2(v.z, v.w);
            #pragma unroll
            for (int i = 0; i < 2; i++) {
                float p = sS[(cg * 2 + i) * 133 + d];
                u64 pd = pk2(p, p);
                fma2(pacc[i][0], pd, v01);
                fma2(pacc[i][1], pd, v23);
            }
        }
        #pragma unroll
        for (int i = 0; i < 2; i++) {
            float2 v0 = upk2(pacc[i][0]);
            float2 v1 = upk2(pacc[i][1]);
            float* row = &sB[(cg * 2 + i) * 36 + lg * 4];
            row[0] = v0.x; row[1] = v0.y; row[2] = v1.x; row[3] = v1.y;
        }
        __syncthreads();

        // grouped 1x1 proj: 16 co x 32 lc = 512 outputs, one per thread
        {
            int co2 = tid >> 5, lc = tid & 31;
            int co = h * 16 + co2;
            float acc = 0.f;
            #pragma unroll
            for (int hh = 0; hh < 8; hh++)
                acc += wo[co * 8 + hh] * sB[(co2 * 8 + hh) * 36 + lc];
            int idx = (b * CCH + co) * LL + l0 + lc;
            g_outcha[idx] = x[idx] + gcha * (acc + bo[co]);
        }
    }
}

// =====================================================================
// Kernel 4: pos proj_out conv3x3 (512->128) GEMM + combine. K=4608.
// =====================================================================
__global__ __launch_bounds__(256, 2) void k_posconv(
    const float* __restrict__ qkv_pos, const float* __restrict__ bo,
    const float* __restrict__ gammap)
{
    const int b  = blockIdx.z;
    const int n0 = blockIdx.x * 128;
    const int tid = threadIdx.x;
    const int tx = tid & 15, ty = tid >> 4;

    __shared__ float As[32][132];
    __shared__ float Bs[32][132];
    u64 acc2[8][4] = {};

    for (int k0 = 0; k0 < 4608; k0 += 32) {
        #pragma unroll
        for (int r = 0; r < 16; r++) {
            int e = r * 256 + tid;
            int kk = e >> 7, m = e & 127;
            As[kk][m] = g_wtpos[(k0 + kk) * 128 + m];
            int k = k0 + kk;
            int tap = k >> 9, ci = k & 511;
            int dy = tap / 3 - 1, dx2 = tap % 3 - 1;
            int l = n0 + m;
            int y = (l >> 4) + dy, xx = (l & 15) + dx2;
            float v = 0.f;
            if ((unsigned)y < 16u && (unsigned)xx < 16u)
                v = g_posatt[(b * EV + ci) * LL + y * 16 + xx];
            Bs[kk][m] = v;
        }
        __syncthreads();
        GEMM_COMPUTE_32(As, Bs, acc2, ty, tx)
        __syncthreads();
    }

    const float gpos = gammap[0];
    #pragma unroll
    for (int i = 0; i < 8; i++) {
        int c = ty * 8 + i;
        float bias = bo[c];
        long base = (long)(b * CCH + c) * LL + n0 + tx * 8;
        #pragma unroll
        for (int jp = 0; jp < 4; jp++) {
            float2 v = upk2(acc2[i][jp]);
            float op0 = qkv_pos[base + 2 * jp]     + gpos * (v.x + bias);
            float op1 = qkv_pos[base + 2 * jp + 1] + gpos * (v.y + bias);
            g_mid[base + 2 * jp]     = 0.5f * (op0 + g_outcha[base + 2 * jp]);
            g_mid[base + 2 * jp + 1] = 0.5f * (op1 + g_outcha[base + 2 * jp + 1]);
        }
    }
}

// =====================================================================
// Kernel 5: fuse conv3x3 (128->128) GEMM -> d_out. K=1152.
// =====================================================================
__global__ __launch_bounds__(256, 2) void k_fuseconv(
    const float* __restrict__ fb, float* __restrict__ out)
{
    const int b  = blockIdx.z;
    const int n0 = blockIdx.x * 128;
    const int tid = threadIdx.x;
    const int tx = tid & 15, ty = tid >> 4;

    __shared__ float As[32][132];
    __shared__ float Bs[32][132];
    u64 acc2[8][4] = {};

    for (int k0 = 0; k0 < 1152; k0 += 32) {
        #pragma unroll
        for (int r = 0; r < 16; r++) {
            int e = r * 256 + tid;
            int kk = e >> 7, m = e & 127;
            As[kk][m] = g_wtfuse[(k0 + kk) * 128 + m];
            int k = k0 + kk;
            int tap = k >> 7, ci = k & 127;
            int dy = tap / 3 - 1, dx2 = tap % 3 - 1;
            int l = n0 + m;
            int y = (l >> 4) + dy, xx = (l & 15) + dx2;
            float v = 0.f;
            if ((unsigned)y < 16u && (unsigned)xx < 16u)
                v = g_mid[(b * CCH + ci) * LL + y * 16 + xx];
            Bs[kk][m] = v;
        }
        __syncthreads();
        GEMM_COMPUTE_32(As, Bs, acc2, ty, tx)
        __syncthreads();
    }

    #pragma unroll
    for (int i = 0; i < 8; i++) {
        int c = ty * 8 + i;
        float bias = fb[c];
        float* dst = &out[(long)(b * CCH + c) * LL + n0 + tx * 8];
        #pragma unroll
        for (int jp = 0; jp < 4; jp++) {
            float2 v = upk2(acc2[i][jp]);
            dst[2 * jp]     = v.x + bias;
            dst[2 * jp + 1] = v.y + bias;
        }
    }
}

// =====================================================================
extern "C" void kernel_launch(void* const* d_in, const int* in_sizes, int n_in,
                              void* d_out, int out_size)
{
    (void)in_sizes; (void)n_in; (void)out_size;
    const float* qkv_pos  = (const float*)d_in[0];
    const float* qkv_cha  = (const float*)d_in[1];
    const float* pos_wq   = (const float*)d_in[2];
    const float* pos_bq   = (const float*)d_in[3];
    const float* pos_wk   = (const float*)d_in[4];
    const float* pos_bk   = (const float*)d_in[5];
    const float* pos_wv   = (const float*)d_in[6];
    const float* pos_bv   = (const float*)d_in[7];
    const float* pos_wo   = (const float*)d_in[8];
    const float* pos_bo   = (const float*)d_in[9];
    const float* gamma_pos= (const float*)d_in[10];
    const float* cha_wq   = (const float*)d_in[11];
    const float* cha_bq   = (const float*)d_in[12];
    const float* cha_wk   = (const float*)d_in[13];
    const float* cha_bk   = (const float*)d_in[14];
    const float* cha_wv   = (const float*)d_in[15];
    const float* cha_bv   = (const float*)d_in[16];
    const float* cha_wo   = (const float*)d_in[17];
    const float* cha_bo   = (const float*)d_in[18];
    const float* gamma_cha= (const float*)d_in[19];
    const float* fuse_w   = (const float*)d_in[20];
    const float* fuse_b   = (const float*)d_in[21];

    cudaFuncSetAttribute(k_pos_attn, cudaFuncAttributeMaxDynamicSharedMemorySize, SMEM_POSATT);
    cudaFuncSetAttribute(k_cha_attn, cudaFuncAttributeMaxDynamicSharedMemorySize, SMEM_CHAATT);

    k_setup<<<1024, 256>>>(pos_wq, pos_wk, pos_wv, pos_bq, pos_bk, pos_bv,
                           pos_wo, fuse_w);

    dim3 g1(2, 6, BATCH);
    k_proj<<<g1, 256>>>(qkv_pos);

    dim3 g2(NHEADS, BATCH);
    k_pos_attn<<<g2, 256, SMEM_POSATT>>>();

    dim3 g3(NHEADS, BATCH);
    k_cha_attn<<<g3, 512, SMEM_CHAATT>>>(qkv_cha, cha_wq, cha_bq, cha_wk, cha_bk,
                                         cha_wv, cha_bv, cha_wo, cha_bo, gamma_cha);

    dim3 g4(2, 1, BATCH);
    k_posconv<<<g4, 256>>>(qkv_pos, pos_bo, gamma_pos);

    dim3 g5(2, 1, BATCH);
    k_fuseconv<<<g5, 256>>>(fuse_b, (float*)d_out);
}

// round 17
// speedup vs baseline: 1.6699x; 1.6699x over previous
#include <cuda_runtime.h>
#include <math.h>

#define BATCH 128
#define CCH   128
#define LL    256
#define NHEADS 8
#define EQK   128
#define EV    512
#define EALL  768   // 128 q + 128 k + 512 v

// ---------------- scratch (device globals; no allocations) ----------------
__device__ float g_proj[BATCH * EALL * LL];
__device__ float g_posatt[BATCH * EV * LL];
__device__ float g_outcha[BATCH * CCH * LL];
__device__ float g_mid[BATCH * CCH * LL];
__device__ float g_wallt[128 * EALL];
__device__ float g_ball[EALL];
__device__ float g_wtpos[4608 * 128];
__device__ float g_wtfuse[1152 * 128];

// ---------------- packed f32x2 helpers ----------------
typedef unsigned long long u64;
__device__ __forceinline__ u64 pk2(float lo, float hi) {
    u64 r; asm("mov.b64 %0, {%1, %2};" : "=l"(r) : "f"(lo), "f"(hi)); return r;
}
__device__ __forceinline__ void fma2(u64& d, u64 a, u64 b) {
    asm("fma.rn.f32x2 %0, %1, %2, %0;" : "+l"(d) : "l"(a), "l"(b));
}
__device__ __forceinline__ void mul2(u64& d, u64 a) {
    asm("mul.rn.f32x2 %0, %0, %1;" : "+l"(d) : "l"(a));
}
__device__ __forceinline__ float2 upk2(u64 v) {
    float2 r; asm("mov.b64 {%0, %1}, %2;" : "=f"(r.x), "=f"(r.y) : "l"(v)); return r;
}

// =====================================================================
// Kernel 0: one-time weight transposes
// =====================================================================
__global__ void k_setup(const float* __restrict__ wq, const float* __restrict__ wk,
                        const float* __restrict__ wv,
                        const float* __restrict__ bq, const float* __restrict__ bk,
                        const float* __restrict__ bv,
                        const float* __restrict__ pwo, const float* __restrict__ fw)
{
    const int total = 98304 + 589824 + 147456 + 768;
    for (int t = blockIdx.x * 256 + threadIdx.x; t < total; t += gridDim.x * 256) {
        if (t < 98304) {
            int c = t / 768, e = t - c * 768;
            float w;
            if (e < 128)      w = wq[e * 128 + c];
            else if (e < 256) w = wk[(e - 128) * 128 + c];
            else              w = wv[(e - 256) * 128 + c];
            g_wallt[t] = w;
        } else if (t < 98304 + 589824) {
            int t2 = t - 98304;
            int k = t2 >> 7, m = t2 & 127;
            int tap = k >> 9, ci = k & 511;
            g_wtpos[t2] = pwo[(m * 512 + ci) * 9 + tap];
        } else if (t < 98304 + 589824 + 147456) {
            int t3 = t - 98304 - 589824;
            int k = t3 >> 7, m = t3 & 127;
            int tap = k >> 7, ci = k & 127;
            g_wtfuse[t3] = fw[(m * 128 + ci) * 9 + tap];
        } else {
            int e = t - (98304 + 589824 + 147456);
            g_ball[e] = (e < 128) ? bq[e] : ((e < 256) ? bk[e - 128] : bv[e - 256]);
        }
    }
}

// ---------------- shared GEMM micro-kernel macro (8x8, f32x2) ----------------
#define GEMM_COMPUTE_32(As, Bs, acc2, ty, tx)                                   \
    _Pragma("unroll")                                                           \
    for (int kk = 0; kk < 32; kk++) {                                           \
        float4 a0 = *(const float4*)&As[kk][(ty) * 8];                          \
        float4 a1 = *(const float4*)&As[kk][(ty) * 8 + 4];                      \
        float4 b0 = *(const float4*)&Bs[kk][(tx) * 8];                          \
        float4 b1 = *(const float4*)&Bs[kk][(tx) * 8 + 4];                      \
        u64 bp[4] = { pk2(b0.x, b0.y), pk2(b0.z, b0.w),                         \
                      pk2(b1.x, b1.y), pk2(b1.z, b1.w) };                       \
        float av[8] = { a0.x, a0.y, a0.z, a0.w, a1.x, a1.y, a1.z, a1.w };       \
        _Pragma("unroll")                                                       \
        for (int i = 0; i < 8; i++) {                                           \
            u64 ad = pk2(av[i], av[i]);                                         \
            _Pragma("unroll")                                                   \
            for (int jp = 0; jp < 4; jp++) fma2(acc2[i][jp], ad, bp[jp]);       \
        }                                                                       \
    }

// =====================================================================
// Kernel 1: positional projections (M=768, N=256, K=128)
// =====================================================================
__global__ __launch_bounds__(256, 2) void k_proj(const float* __restrict__ x)
{
    const int b  = blockIdx.z;
    const int m0 = blockIdx.y * 128;
    const int n0 = blockIdx.x * 128;
    const int tid = threadIdx.x;
    const int tx = tid & 15, ty = tid >> 4;

    __shared__ float As[32][132];
    __shared__ float Bs[32][132];
    u64 acc2[8][4] = {};

    for (int k0 = 0; k0 < 128; k0 += 32) {
        #pragma unroll
        for (int r = 0; r < 16; r++) {
            int e = r * 256 + tid;
            int kk = e >> 7, m = e & 127;
            As[kk][m] = g_wallt[(k0 + kk) * EALL + m0 + m];
            Bs[kk][m] = x[(b * CCH + k0 + kk) * LL + n0 + m];
        }
        __syncthreads();
        GEMM_COMPUTE_32(As, Bs, acc2, ty, tx)
        __syncthreads();
    }

    #pragma unroll
    for (int i = 0; i < 8; i++) {
        int e = m0 + ty * 8 + i;
        float bias = g_ball[e];
        float* dst = &g_proj[(b * EALL + e) * LL + n0 + tx * 8];
        #pragma unroll
        for (int jp = 0; jp < 4; jp++) {
            float2 v = upk2(acc2[i][jp]);
            dst[jp * 2 + 0] = v.x + bias;
            dst[jp * 2 + 1] = v.y + bias;
        }
    }
}

// =====================================================================
// Kernel 2: positional attention per (b,h). Online softmax, f32x2 PV.
// =====================================================================
#define SMEM_POSATT ((256*20 + 256*68) * 4)
__global__ __launch_bounds__(256) void k_pos_attn()
{
    const int h = blockIdx.x, b = blockIdx.y;
    const int tid = threadIdx.x;
    extern __shared__ float sm2[];
    float* sk = sm2;
    float* sv = sk + 256 * 20;

    #pragma unroll
    for (int r = 0; r < 16; r++)
        sk[tid * 20 + r] = g_proj[(b * EALL + 128 + h * 16 + r) * LL + tid];
    #pragma unroll
    for (int r = 0; r < 64; r++)
        sv[tid * 68 + r] = g_proj[(b * EALL + 256 + h * 64 + r) * LL + tid];

    u64 qp[8];
    {
        float q[16];
        #pragma unroll
        for (int r = 0; r < 16; r++)
            q[r] = g_proj[(b * EALL + h * 16 + r) * LL + tid];
        #pragma unroll
        for (int i = 0; i < 8; i++) qp[i] = pk2(q[2 * i], q[2 * i + 1]);
    }
    __syncthreads();

    float mx = -1e30f, s = 0.f;
    u64 acc2[32];
    #pragma unroll
    for (int j = 0; j < 32; j++) acc2[j] = 0ull;

    for (int k = 0; k < 256; k++) {
        const float4* kp = (const float4*)(sk + k * 20);
        u64 d2 = 0ull;
        #pragma unroll
        for (int q4 = 0; q4 < 4; q4++) {
            float4 kv = kp[q4];
            fma2(d2, qp[q4 * 2 + 0], pk2(kv.x, kv.y));
            fma2(d2, qp[q4 * 2 + 1], pk2(kv.z, kv.w));
        }
        float2 dd = upk2(d2);
        float sc = (dd.x + dd.y) * 0.25f;

        float p;
        if (sc > mx) {
            float corr = __expf(mx - sc);
            s *= corr;
            u64 c2 = pk2(corr, corr);
            #pragma unroll
            for (int j = 0; j < 32; j++) mul2(acc2[j], c2);
            mx = sc; p = 1.f;
        } else {
            p = __expf(sc - mx);
        }
        s += p;

        u64 pp = pk2(p, p);
        const float4* vp = (const float4*)(sv + k * 68);
        #pragma unroll
        for (int j4 = 0; j4 < 16; j4++) {
            float4 v = vp[j4];
            fma2(acc2[j4 * 2 + 0], pp, pk2(v.x, v.y));
            fma2(acc2[j4 * 2 + 1], pp, pk2(v.z, v.w));
        }
    }
    float inv = 1.f / s;
    #pragma unroll
    for (int j = 0; j < 32; j++) {
        float2 v = upk2(acc2[j]);
        g_posatt[(b * EV + h * 64 + 2 * j + 0) * LL + tid] = v.x * inv;
        g_posatt[(b * EV + h * 64 + 2 * j + 1) * LL + tid] = v.y * inv;
    }
}

// =====================================================================
// Kernel 3: channel attention per (b,h'), fully fused — 256 threads
// (proven R2 structure) with VECTORIZED inner loops (LDS.128).
// smem: sS[128][132] + sA[128][36] + sB[128][36] = 104448 B
// =====================================================================
#define SMEM_CHAATT ((128*132 + 128*36*2) * 4)
__global__ __launch_bounds__(256) void k_cha_attn(
    const float* __restrict__ x,
    const float* __restrict__ wq, const float* __restrict__ bq,
    const float* __restrict__ wk, const float* __restrict__ bk,
    const float* __restrict__ wv, const float* __restrict__ bv,
    const float* __restrict__ wo, const float* __restrict__ bo,
    const float* __restrict__ gammap)
{
    const int h = blockIdx.x, b = blockIdx.y;
    const int tid = threadIdx.x;
    const int tx = tid & 15, ty = tid >> 4;
    extern __shared__ float sm3[];
    float* sS = sm3;               // [128][132]  (132 = 33*4, 16B-aligned rows)
    float* sA = sS + 128 * 132;    // [128][36]
    float* sB = sA + 128 * 36;     // [128][36]

    // ---- phase 1: S[c][d] = (1/16) sum_l pq[c,l] pk[d,l]; 4 k-steps batched ----
    u64 facc2[8][4] = {};
    for (int l0 = 0; l0 < 256; l0 += 32) {
        __syncthreads();
        #pragma unroll
        for (int r = 0; r < 16; r++) {
            int e = r * 256 + tid;
            int c = e >> 5, lc = e & 31;
            int j = h * 128 + c;
            float xv = x[(b * CCH + (j >> 3)) * LL + l0 + lc];
            sA[c * 36 + lc] = xv * wq[j] + bq[j];
            sB[c * 36 + lc] = xv * wk[j] + bk[j];
        }
        __syncthreads();
        #pragma unroll
        for (int lc4 = 0; lc4 < 8; lc4++) {
            float4 avv[8], bvv[8];
            #pragma unroll
            for (int i = 0; i < 8; i++)
                avv[i] = *(const float4*)&sA[(ty + 16 * i) * 36 + lc4 * 4];
            #pragma unroll
            for (int j = 0; j < 8; j++)
                bvv[j] = *(const float4*)&sB[(tx + 16 * j) * 36 + lc4 * 4];
            #pragma unroll
            for (int kk = 0; kk < 4; kk++) {
                u64 bp[4];
                #pragma unroll
                for (int jp = 0; jp < 4; jp++) {
                    const float* b0 = (const float*)&bvv[2 * jp];
                    const float* b1 = (const float*)&bvv[2 * jp + 1];
                    bp[jp] = pk2(b0[kk], b1[kk]);
                }
                #pragma unroll
                for (int i = 0; i < 8; i++) {
                    const float* ap = (const float*)&avv[i];
                    u64 ad = pk2(ap[kk], ap[kk]);
                    #pragma unroll
                    for (int jp = 0; jp < 4; jp++) fma2(facc2[i][jp], ad, bp[jp]);
                }
            }
        }
    }
    __syncthreads();
    #pragma unroll
    for (int i = 0; i < 8; i++)
        #pragma unroll
        for (int jp = 0; jp < 4; jp++) {
            float2 v = upk2(facc2[i][jp]);
            sS[(ty + 16 * i) * 132 + tx + 16 * (2 * jp + 0)] = v.x * 0.0625f;
            sS[(ty + 16 * i) * 132 + tx + 16 * (2 * jp + 1)] = v.y * 0.0625f;
        }
    __syncthreads();

    // ---- phase 2: softmax over d (128 rows) ----
    if (tid < 128) {
        float* row = sS + tid * 132;
        float m = -1e30f;
        #pragma unroll 8
        for (int i = 0; i < 32; i++) {
            float4 v = *(const float4*)&row[i * 4];
            m = fmaxf(m, fmaxf(fmaxf(v.x, v.y), fmaxf(v.z, v.w)));
        }
        float sum = 0.f;
        #pragma unroll 8
        for (int i = 0; i < 32; i++) {
            float4 v = *(float4*)&row[i * 4];
            v.x = __expf(v.x - m); v.y = __expf(v.y - m);
            v.z = __expf(v.z - m); v.w = __expf(v.w - m);
            sum += v.x + v.y + v.z + v.w;
            *(float4*)&row[i * 4] = v;
        }
        float invs = 1.f / sum;
        #pragma unroll 8
        for (int i = 0; i < 32; i++) {
            float4 v = *(float4*)&row[i * 4];
            v.x *= invs; v.y *= invs; v.z *= invs; v.w *= invs;
            *(float4*)&row[i * 4] = v;
        }
    }
    __syncthreads();

    // ---- phase 3: out = P @ pv (4x4 per thread), 4 d-steps batched ----
    const float gcha = gammap[0];
    const int cg = tid >> 3;      // 0..31 -> c = cg*4 + i
    const int lg = tid & 7;       // 0..7  -> lc = lg*4 + j
    for (int l0 = 0; l0 < 256; l0 += 32) {
        __syncthreads();
        #pragma unroll
        for (int r = 0; r < 16; r++) {
            int e = r * 256 + tid;
            int c = e >> 5, lc = e & 31;
            int j = h * 128 + c;
            float xv = x[(b * CCH + (j >> 3)) * LL + l0 + lc];
            sA[c * 36 + lc] = xv * wv[j] + bv[j];
        }
        __syncthreads();

        u64 pacc[4][2] = {};
        #pragma unroll 4
        for (int d4 = 0; d4 < 32; d4++) {
            float4 pr[4];
            #pragma unroll
            for (int i = 0; i < 4; i++)
                pr[i] = *(const float4*)&sS[(cg * 4 + i) * 132 + d4 * 4];
            #pragma unroll
            for (int dd = 0; dd < 4; dd++) {
                float4 v = *(const float4*)&sA[(d4 * 4 + dd) * 36 + lg * 4];
                u64 v01 = pk2(v.x, v.y), v23 = pk2(v.z, v.w);
                #pragma unroll
                for (int i = 0; i < 4; i++) {
                    const float* pp = (const float*)&pr[i];
                    u64 pd = pk2(pp[dd], pp[dd]);
                    fma2(pacc[i][0], pd, v01);
                    fma2(pacc[i][1], pd, v23);
                }
            }
        }
        #pragma unroll
        for (int i = 0; i < 4; i++) {
            float2 v0 = upk2(pacc[i][0]);
            float2 v1 = upk2(pacc[i][1]);
            float* row = &sB[(cg * 4 + i) * 36 + lg * 4];
            row[0] = v0.x; row[1] = v0.y; row[2] = v1.x; row[3] = v1.y;
        }
        __syncthreads();

        // grouped 1x1 proj: out channel co = h*16+co2 sums rows co2*8+hh
        #pragma unroll
        for (int r2 = 0; r2 < 2; r2++) {
            int e = r2 * 256 + tid;
            int co2 = e >> 5, lc = e & 31;
            int co = h * 16 + co2;
            float acc = 0.f;
            #pragma unroll
            for (int hh = 0; hh < 8; hh++)
                acc += wo[co * 8 + hh] * sB[(co2 * 8 + hh) * 36 + lc];
            int idx = (b * CCH + co) * LL + l0 + lc;
            g_outcha[idx] = x[idx] + gcha * (acc + bo[co]);
        }
    }
}

// =====================================================================
// Kernel 4: pos proj_out conv3x3 (512->128) GEMM + combine. K=4608.
// =====================================================================
__global__ __launch_bounds__(256, 2) void k_posconv(
    const float* __restrict__ qkv_pos, const float* __restrict__ bo,
    const float* __restrict__ gammap)
{
    const int b  = blockIdx.z;
    const int n0 = blockIdx.x * 128;
    const int tid = threadIdx.x;
    const int tx = tid & 15, ty = tid >> 4;

    __shared__ float As[32][132];
    __shared__ float Bs[32][132];
    u64 acc2[8][4] = {};

    for (int k0 = 0; k0 < 4608; k0 += 32) {
        #pragma unroll
        for (int r = 0; r < 16; r++) {
            int e = r * 256 + tid;
            int kk = e >> 7, m = e & 127;
            As[kk][m] = g_wtpos[(k0 + kk) * 128 + m];
            int k = k0 + kk;
            int tap = k >> 9, ci = k & 511;
            int dy = tap / 3 - 1, dx2 = tap % 3 - 1;
            int l = n0 + m;
            int y = (l >> 4) + dy, xx = (l & 15) + dx2;
            float v = 0.f;
            if ((unsigned)y < 16u && (unsigned)xx < 16u)
                v = g_posatt[(b * EV + ci) * LL + y * 16 + xx];
            Bs[kk][m] = v;
        }
        __syncthreads();
        GEMM_COMPUTE_32(As, Bs, acc2, ty, tx)
        __syncthreads();
    }

    const float gpos = gammap[0];
    #pragma unroll
    for (int i = 0; i < 8; i++) {
        int c = ty * 8 + i;
        float bias = bo[c];
        long base = (long)(b * CCH + c) * LL + n0 + tx * 8;
        #pragma unroll
        for (int jp = 0; jp < 4; jp++) {
            float2 v = upk2(acc2[i][jp]);
            float op0 = qkv_pos[base + 2 * jp]     + gpos * (v.x + bias);
            float op1 = qkv_pos[base + 2 * jp + 1] + gpos * (v.y + bias);
            g_mid[base + 2 * jp]     = 0.5f * (op0 + g_outcha[base + 2 * jp]);
            g_mid[base + 2 * jp + 1] = 0.5f * (op1 + g_outcha[base + 2 * jp + 1]);
        }
    }
}

// =====================================================================
// Kernel 5: fuse conv3x3 (128->128) GEMM -> d_out. K=1152.
// =====================================================================
__global__ __launch_bounds__(256, 2) void k_fuseconv(
    const float* __restrict__ fb, float* __restrict__ out)
{
    const int b  = blockIdx.z;
    const int n0 = blockIdx.x * 128;
    const int tid = threadIdx.x;
    const int tx = tid & 15, ty = tid >> 4;

    __shared__ float As[32][132];
    __shared__ float Bs[32][132];
    u64 acc2[8][4] = {};

    for (int k0 = 0; k0 < 1152; k0 += 32) {
        #pragma unroll
        for (int r = 0; r < 16; r++) {
            int e = r * 256 + tid;
            int kk = e >> 7, m = e & 127;
            As[kk][m] = g_wtfuse[(k0 + kk) * 128 + m];
            int k = k0 + kk;
            int tap = k >> 7, ci = k & 127;
            int dy = tap / 3 - 1, dx2 = tap % 3 - 1;
            int l = n0 + m;
            int y = (l >> 4) + dy, xx = (l & 15) + dx2;
            float v = 0.f;
            if ((unsigned)y < 16u && (unsigned)xx < 16u)
                v = g_mid[(b * CCH + ci) * LL + y * 16 + xx];
            Bs[kk][m] = v;
        }
        __syncthreads();
        GEMM_COMPUTE_32(As, Bs, acc2, ty, tx)
        __syncthreads();
    }

    #pragma unroll
    for (int i = 0; i < 8; i++) {
        int c = ty * 8 + i;
        float bias = fb[c];
        float* dst = &out[(long)(b * CCH + c) * LL + n0 + tx * 8];
        #pragma unroll
        for (int jp = 0; jp < 4; jp++) {
            float2 v = upk2(acc2[i][jp]);
            dst[2 * jp]     = v.x + bias;
            dst[2 * jp + 1] = v.y + bias;
        }
    }
}

// =====================================================================
extern "C" void kernel_launch(void* const* d_in, const int* in_sizes, int n_in,
                              void* d_out, int out_size)
{
    (void)in_sizes; (void)n_in; (void)out_size;
    const float* qkv_pos  = (const float*)d_in[0];
    const float* qkv_cha  = (const float*)d_in[1];
    const float* pos_wq   = (const float*)d_in[2];
    const float* pos_bq   = (const float*)d_in[3];
    const float* pos_wk   = (const float*)d_in[4];
    const float* pos_bk   = (const float*)d_in[5];
    const float* pos_wv   = (const float*)d_in[6];
    const float* pos_bv   = (const float*)d_in[7];
    const float* pos_wo   = (const float*)d_in[8];
    const float* pos_bo   = (const float*)d_in[9];
    const float* gamma_pos= (const float*)d_in[10];
    const float* cha_wq   = (const float*)d_in[11];
    const float* cha_bq   = (const float*)d_in[12];
    const float* cha_wk   = (const float*)d_in[13];
    const float* cha_bk   = (const float*)d_in[14];
    const float* cha_wv   = (const float*)d_in[15];
    const float* cha_bv   = (const float*)d_in[16];
    const float* cha_wo   = (const float*)d_in[17];
    const float* cha_bo   = (const float*)d_in[18];
    const float* gamma_cha= (const float*)d_in[19];
    const float* fuse_w   = (const float*)d_in[20];
    const float* fuse_b   = (const float*)d_in[21];

    cudaFuncSetAttribute(k_pos_attn, cudaFuncAttributeMaxDynamicSharedMemorySize, SMEM_POSATT);
    cudaFuncSetAttribute(k_cha_attn, cudaFuncAttributeMaxDynamicSharedMemorySize, SMEM_CHAATT);

    k_setup<<<1024, 256>>>(pos_wq, pos_wk, pos_wv, pos_bq, pos_bk, pos_bv,
                           pos_wo, fuse_w);

    dim3 g1(2, 6, BATCH);
    k_proj<<<g1, 256>>>(qkv_pos);

    dim3 g2(NHEADS, BATCH);
    k_pos_attn<<<g2, 256, SMEM_POSATT>>>();

    dim3 g3(NHEADS, BATCH);
    k_cha_attn<<<g3, 256, SMEM_CHAATT>>>(qkv_cha, cha_wq, cha_bq, cha_wk, cha_bk,
                                         cha_wv, cha_bv, cha_wo, cha_bo, gamma_cha);

    dim3 g4(2, 1, BATCH);
    k_posconv<<<g4, 256>>>(qkv_pos, pos_bo, gamma_pos);

    dim3 g5(2, 1, BATCH);
    k_fuseconv<<<g5, 256>>>(fuse_b, (float*)d_out);
}